// round 16
// baseline (speedup 1.0000x reference)
#include <cuda_runtime.h>
#include <cuda_fp16.h>
#include <cstdint>

// PatchMerged fused: Haar-DWT2 + LayerNorm + (384->192) GEMM, fp16 mma.sync.
// Split-N persistent CTAs: each CTA owns a 96-col weight half (72KB resident),
// 2 CTAs/SM for cross-CTA phase overlap. M-tile = 128 pixels, full K=384 per CTA.
// Single-sync double-buffered mainloop + cross-tile register prefetch (R10 loop).
// out[b, l, d] = r*(G - mu*s[d]) + t[d],  G = patch @ W4
//   mu = sum_c x[b,c,2h,2w]/192 ; var = sum_patch x^2/384 - mu^2  (Haar identities)

__device__ __align__(16) __half g_Wh[73728];   // 6 chunks x [192 n-rows x 64 k] swizzled
__device__ float2 g_st2[192];                  // (s,t) folded reduction vectors

// ---- prep (merged): blocks <288 fold Haar+gamma into swizzled W4 image;
//      blocks >=288 compute per-d (s,t) ----
__global__ void pm_prep(const float* __restrict__ nw, const float* __restrict__ nb,
                        const float* __restrict__ wr) {
    if (blockIdx.x < 288) {
        int idx = blockIdx.x * 256 + threadIdx.x;
        if (idx >= 384 * 192) return;
        int kg = idx / 192, d = idx - kg * 192;
        int c = kg >> 2, q = kg & 3, dy = q >> 1, dx = q & 1;
        float wll = nw[c]       * wr[c * 192 + d];
        float wlh = nw[96 + c]  * wr[(96 + c) * 192 + d];
        float whl = nw[192 + c] * wr[(192 + c) * 192 + d];
        float whh = nw[288 + c] * wr[(288 + c) * 192 + d];
        float v = 0.5f * (wll + (dy ? -wlh : wlh) + (dx ? -whl : whl)
                              + ((dx ^ dy) ? -whh : whh));
        int ck = c >> 4, kl = ((c & 15) << 2) | q;       // chunk 0..5, k-local 0..63
        int off = ck * 24576 + d * 128 + ((((kl >> 3) ^ (d & 7)) << 4)) + (kl & 7) * 2;
        g_Wh[off >> 1] = __float2half_rn(v);
    } else {
        __shared__ float rs[8], rt[8];
        const int d = blockIdx.x - 288, tid = threadIdx.x;
        float s = 0.f, t = 0.f;
        for (int yc = tid; yc < 384; yc += 256) {
            float w = wr[yc * 192 + d];
            s += nw[yc] * w; t += nb[yc] * w;
        }
        #pragma unroll
        for (int o = 16; o > 0; o >>= 1) {
            s += __shfl_down_sync(0xffffffffu, s, o);
            t += __shfl_down_sync(0xffffffffu, t, o);
        }
        if ((tid & 31) == 0) { rs[tid >> 5] = s; rt[tid >> 5] = t; }
        __syncthreads();
        if (tid == 0) {
            float fs = 0.f, ft = 0.f;
            #pragma unroll
            for (int i = 0; i < 8; i++) { fs += rs[i]; ft += rt[i]; }
            g_st2[d] = make_float2(fs, ft);
        }
    }
}

__device__ __forceinline__ uint32_t smem_u32(const void* p) {
    uint32_t a;
    asm("{ .reg .u64 t; cvta.to.shared.u64 t, %1; cvt.u32.u64 %0, t; }" : "=r"(a) : "l"(p));
    return a;
}

// SMEM map (dynamic, 109056 B per CTA; 2 CTAs/SM)
static constexpr int SM_W   = 0;         // 73728: weight half (6 chunks x 96 rows)
static constexpr int SM_A   = 73728;     // 2 x 16384: A fp16 (128r x 64k, swizzled)
static constexpr int SM_RED = 73728;     // stats overlay on A buf0 (8KB; safe post-MMA)
static constexpr int SM_MU  = 106496;    // 128 f32
static constexpr int SM_RR  = 107008;    // 128 f32
static constexpr int SM_ST  = 107520;    // 192 float2
static constexpr int SMEM_SZ = 109056;
static constexpr int NTILE = 2048;

// per-chunk x load: warp wid owns channels {16ck+2wid, +1}; lanes x j cover 128 pixels
#define LDGX(tt, ck) do {                                                              \
    int bb = (tt) >> 7, hh = (tt) & 127;                                               \
    _Pragma("unroll") for (int ci = 0; ci < 2; ci++)                                   \
    _Pragma("unroll") for (int dy = 0; dy < 2; dy++)                                   \
    _Pragma("unroll") for (int j = 0; j < 4; j++)                                      \
        pf[ci][dy][j] = *(const float2*)(x +                                           \
            (((size_t)bb * 96 + (ck) * 16 + 2 * wid + ci) * 256                        \
             + 2 * hh + dy) * 256 + 2 * (lane + 32 * j));                              \
} while (0)

__global__ void __launch_bounds__(256, 2)
pm_main(const float* __restrict__ x, float* __restrict__ out) {
    extern __shared__ char smem[];
    const uint32_t sb = smem_u32(smem);
    const int tid = threadIdx.x, lane = tid & 31, wid = tid >> 5;
    const int gid = lane >> 2, t4 = lane & 3;
    const int wh = wid >> 1, wn = wid & 1;    // MMA warp grid: 4 (M) x 2 (N)
    const int l7 = lane & 7;
    const int nh = blockIdx.x & 1;            // N-half: cols [nh*96, nh*96+96)
    const int t0 = blockIdx.x >> 1;           // first tile; stride 148

    // ldmatrix per-lane row-offset bases (tile select via lane bits 3,4)
    const uint32_t arow_off = (uint32_t)((wh * 32 + l7 + ((lane >> 3) & 1) * 8) * 128);
    const uint32_t brow_off = (uint32_t)((wn * 48 + l7 + (lane >> 4) * 8) * 128);
    const int ga_sel = lane >> 4;          // A k-granule bit
    const int gb_sel = (lane >> 3) & 1;    // B k-granule bit

    // ---- stage this CTA's weight half (96 rows per chunk) + st table ----
    {
        #pragma unroll
        for (int i = 0; i < 18; i++) {
            int u = tid + 256 * i;                       // 16B unit, 0..4607
            int ck = u / 768, r = u - ck * 768;          // 768 units per chunk half
            const char* src = (const char*)g_Wh + ck * 24576 + nh * 12288 + r * 16;
            asm volatile("cp.async.cg.shared.global [%0], [%1], 16;"
                         :: "r"(sb + SM_W + u * 16),
                            "l"(__cvta_generic_to_global(src)) : "memory");
        }
        asm volatile("cp.async.commit_group;" ::: "memory");
        asm volatile("cp.async.wait_group 0;" ::: "memory");
    }
    if (tid < 192) *(float2*)(smem + SM_ST + tid * 8) = g_st2[tid];
    __syncthreads();

    float2 pf[2][2][4];
    if (t0 < NTILE) LDGX(t0, 0);

    for (int t = t0; t < NTILE; t += 148) {
        const int b = t >> 7, h = t & 127;

        float acc[2][6][4];
        #pragma unroll
        for (int i = 0; i < 2; i++)
        #pragma unroll
        for (int j = 0; j < 6; j++)
        #pragma unroll
        for (int q = 0; q < 4; q++) acc[i][j][q] = 0.f;
        float ssum_t[4] = {0, 0, 0, 0}, ssq_t[4] = {0, 0, 0, 0};

        #pragma unroll 1
        for (int ck = 0; ck < 6; ++ck) {
            const uint32_t abuf = sb + SM_A + (uint32_t)((ck & 1) << 14);
            // ---- A: stats (raw f32) + fp16 convert + swizzled STS.128 ----
            // (safe without pre-sync: every warp's MMA(ck-2) ldmatrix reads of this
            //  buffer were issued before it arrived at sync(ck-1))
            #pragma unroll
            for (int j = 0; j < 4; j++) {
                const int p = lane + 32 * j;
                float2 v00 = pf[0][0][j], v01 = pf[0][1][j];
                float2 v10 = pf[1][0][j], v11 = pf[1][1][j];
                ssum_t[j] += v00.x + v10.x;
                ssq_t[j]  += v00.x * v00.x + v00.y * v00.y + v01.x * v01.x + v01.y * v01.y
                           + v10.x * v10.x + v10.y * v10.y + v11.x * v11.x + v11.y * v11.y;
                __half2 h0 = __floats2half2_rn(v00.x, v00.y);
                __half2 h1 = __floats2half2_rn(v01.x, v01.y);
                __half2 h2 = __floats2half2_rn(v10.x, v10.y);
                __half2 h3 = __floats2half2_rn(v11.x, v11.y);
                asm volatile("st.shared.v4.b32 [%0], {%1,%2,%3,%4};"
                             :: "r"(abuf + p * 128 + ((wid ^ (p & 7)) << 4)),
                                "r"(*(uint32_t*)&h0), "r"(*(uint32_t*)&h1),
                                "r"(*(uint32_t*)&h2), "r"(*(uint32_t*)&h3) : "memory");
            }
            // ---- next loads BEFORE the barrier (latency hides under MMA+sync) ----
            if (ck < 5) {
                LDGX(t, ck + 1);
            } else if (t + 148 < NTILE) {
                LDGX(t + 148, 0);                        // next tile's chunk 0
            }
            __syncthreads();                 // A(ck) visible to all warps
            // ---- MMA on chunk ck ----
            const uint32_t wck = sb + SM_W + (uint32_t)(ck * 12288);
            #pragma unroll
            for (int s = 0; s < 4; s++) {
                uint32_t ua[2][4], ub[6][2];
                const uint32_t xa = (uint32_t)((((2 * s + ga_sel) ^ l7)) << 4);
                const uint32_t xb = (uint32_t)((((2 * s + gb_sel) ^ l7)) << 4);
                #pragma unroll
                for (int mt = 0; mt < 2; mt++)
                    asm volatile(
                        "ldmatrix.sync.aligned.m8n8.x4.shared.b16 {%0,%1,%2,%3}, [%4];"
                        : "=r"(ua[mt][0]), "=r"(ua[mt][1]),
                          "=r"(ua[mt][2]), "=r"(ua[mt][3])
                        : "r"(abuf + arow_off + mt * 2048 + xa));
                #pragma unroll
                for (int p = 0; p < 3; p++)
                    asm volatile(
                        "ldmatrix.sync.aligned.m8n8.x4.shared.b16 {%0,%1,%2,%3}, [%4];"
                        : "=r"(ub[2 * p][0]), "=r"(ub[2 * p][1]),
                          "=r"(ub[2 * p + 1][0]), "=r"(ub[2 * p + 1][1])
                        : "r"(wck + brow_off + p * 2048 + xb));
                #pragma unroll
                for (int mt = 0; mt < 2; mt++)
                #pragma unroll
                for (int nt = 0; nt < 6; nt++)
                    asm volatile(
                        "mma.sync.aligned.m16n8k16.row.col.f32.f16.f16.f32 "
                        "{%0,%1,%2,%3}, {%4,%5,%6,%7}, {%8,%9}, {%0,%1,%2,%3};"
                        : "+f"(acc[mt][nt][0]), "+f"(acc[mt][nt][1]),
                          "+f"(acc[mt][nt][2]), "+f"(acc[mt][nt][3])
                        : "r"(ua[mt][0]), "r"(ua[mt][1]), "r"(ua[mt][2]), "r"(ua[mt][3]),
                          "r"(ub[nt][0]), "r"(ub[nt][1]));
            }
        }

        // ---- LN stats: per-(warp,pixel) partials -> mu, 1/sigma ----
        // RED overlays A buf0: chunk-4 (buf0) ldmatrix reads were issued before
        // sync(5), which all warps have passed (same argument as buffer reuse).
        #pragma unroll
        for (int j = 0; j < 4; j++) {
            int p = lane + 32 * j;
            *(float*)(smem + SM_RED + (wid * 128 + p) * 4)        = ssum_t[j];
            *(float*)(smem + SM_RED + 4096 + (wid * 128 + p) * 4) = ssq_t[j];
        }
        __syncthreads();
        if (tid < 128) {
            float s = 0.f, qq = 0.f;
            #pragma unroll
            for (int w = 0; w < 8; w++) {
                s  += *(float*)(smem + SM_RED + (w * 128 + tid) * 4);
                qq += *(float*)(smem + SM_RED + 4096 + (w * 128 + tid) * 4);
            }
            float mu = s * (1.f / 192.f);
            float var = qq * (1.f / 384.f) - mu * mu;
            *(float*)(smem + SM_MU + tid * 4) = mu;
            *(float*)(smem + SM_RR + tid * 4) = rsqrtf(var + 1e-5f);
        }
        __syncthreads();   // RED reads done -> next tile may overwrite buf0; mu/rr ready

        // ---- fused epilogue from register accumulators (this CTA's 96 cols) ----
        float* ob = out + ((size_t)b * 16384 + (size_t)h * 128) * 192;
        #pragma unroll
        for (int mt = 0; mt < 2; mt++) {
            int row0 = wh * 32 + mt * 16 + gid;
            float mu0 = *(float*)(smem + SM_MU + row0 * 4);
            float r0  = *(float*)(smem + SM_RR + row0 * 4);
            float mu1 = *(float*)(smem + SM_MU + (row0 + 8) * 4);
            float r1  = *(float*)(smem + SM_RR + (row0 + 8) * 4);
            #pragma unroll
            for (int nt = 0; nt < 6; nt++) {
                int cb = nh * 96 + wn * 48 + nt * 8 + 2 * t4;
                float2 st0 = *(const float2*)(smem + SM_ST + cb * 8);
                float2 st1 = *(const float2*)(smem + SM_ST + cb * 8 + 8);
                float2 v0, v1;
                v0.x = r0 * (acc[mt][nt][0] - mu0 * st0.x) + st0.y;
                v0.y = r0 * (acc[mt][nt][1] - mu0 * st1.x) + st1.y;
                v1.x = r1 * (acc[mt][nt][2] - mu1 * st0.x) + st0.y;
                v1.y = r1 * (acc[mt][nt][3] - mu1 * st1.x) + st1.y;
                *(float2*)(ob + (size_t)row0 * 192 + cb)       = v0;
                *(float2*)(ob + (size_t)(row0 + 8) * 192 + cb) = v1;
            }
        }
    }
}

extern "C" void kernel_launch(void* const* d_in, const int* in_sizes, int n_in,
                              void* d_out, int out_size) {
    const float* x  = (const float*)d_in[0];
    const float* nw = (const float*)d_in[1];
    const float* nb = (const float*)d_in[2];
    const float* wr = (const float*)d_in[3];
    float* out = (float*)d_out;
    (void)in_sizes; (void)n_in; (void)out_size;

    static int cfg = 0;
    if (!cfg) {
        cudaFuncSetAttribute(pm_main, cudaFuncAttributeMaxDynamicSharedMemorySize, SMEM_SZ);
        cfg = 1;
    }
    pm_prep<<<480, 256>>>(nw, nb, wr);
    pm_main<<<296, 256, SMEM_SZ>>>(x, out);
}

// round 17
// speedup vs baseline: 1.6191x; 1.6191x over previous
#include <cuda_runtime.h>
#include <cuda_fp16.h>
#include <cstdint>

// PatchMerged fused: Haar-DWT2 + LayerNorm + (384->192) GEMM, fp16 mma.sync.
// Persistent 256-thread CTAs, weight-resident SMEM, M-tile = 128 pixels.
// Software-pipelined chunk loop: 3-stage A ring, STS interleaved between MMA
// halves, LDG 1.5 chunks ahead, one barrier per chunk.
// out[b, l, d] = r*(G - mu*s[d]) + t[d],  G = patch @ W4
//   mu = sum_c x[b,c,2h,2w]/192 ; var = sum_patch x^2/384 - mu^2  (Haar identities)

__device__ __align__(16) __half g_Wh[73728];   // 6 chunks x [192 n-rows x 64 k] swizzled
__device__ float2 g_st2[192];                  // (s,t) folded reduction vectors

// ---- prep (merged): blocks <288 fold Haar+gamma into swizzled W4 image;
//      blocks >=288 compute per-d (s,t) ----
__global__ void pm_prep(const float* __restrict__ nw, const float* __restrict__ nb,
                        const float* __restrict__ wr) {
    if (blockIdx.x < 288) {
        int idx = blockIdx.x * 256 + threadIdx.x;
        if (idx >= 384 * 192) return;
        int kg = idx / 192, d = idx - kg * 192;
        int c = kg >> 2, q = kg & 3, dy = q >> 1, dx = q & 1;
        float wll = nw[c]       * wr[c * 192 + d];
        float wlh = nw[96 + c]  * wr[(96 + c) * 192 + d];
        float whl = nw[192 + c] * wr[(192 + c) * 192 + d];
        float whh = nw[288 + c] * wr[(288 + c) * 192 + d];
        float v = 0.5f * (wll + (dy ? -wlh : wlh) + (dx ? -whl : whl)
                              + ((dx ^ dy) ? -whh : whh));
        int ck = c >> 4, kl = ((c & 15) << 2) | q;       // chunk 0..5, k-local 0..63
        int off = ck * 24576 + d * 128 + ((((kl >> 3) ^ (d & 7)) << 4)) + (kl & 7) * 2;
        g_Wh[off >> 1] = __float2half_rn(v);
    } else {
        __shared__ float rs[8], rt[8];
        const int d = blockIdx.x - 288, tid = threadIdx.x;
        float s = 0.f, t = 0.f;
        for (int yc = tid; yc < 384; yc += 256) {
            float w = wr[yc * 192 + d];
            s += nw[yc] * w; t += nb[yc] * w;
        }
        #pragma unroll
        for (int o = 16; o > 0; o >>= 1) {
            s += __shfl_down_sync(0xffffffffu, s, o);
            t += __shfl_down_sync(0xffffffffu, t, o);
        }
        if ((tid & 31) == 0) { rs[tid >> 5] = s; rt[tid >> 5] = t; }
        __syncthreads();
        if (tid == 0) {
            float fs = 0.f, ft = 0.f;
            #pragma unroll
            for (int i = 0; i < 8; i++) { fs += rs[i]; ft += rt[i]; }
            g_st2[d] = make_float2(fs, ft);
        }
    }
}

__device__ __forceinline__ uint32_t smem_u32(const void* p) {
    uint32_t a;
    asm("{ .reg .u64 t; cvta.to.shared.u64 t, %1; cvt.u32.u64 %0, t; }" : "=r"(a) : "l"(p));
    return a;
}

// SMEM map (dynamic, 207360 B)
static constexpr int SM_W   = 0;         // 147456: weight image (6 chunks)
static constexpr int SM_A   = 147456;    // 3 x 16384: A fp16 ring (128r x 64k, swizzled)
static constexpr int SM_RED = 196608;    // 8x128 sums | 8x128 ssq (8192 B)
static constexpr int SM_MU  = 204800;    // 128 f32
static constexpr int SM_RR  = 205312;    // 128 f32
static constexpr int SM_ST  = 205824;    // 192 float2
static constexpr int SMEM_SZ = 207360;
static constexpr int NTILE = 2048;

// per-chunk x load: warp wid owns channels {16ck+2wid, +1}; lanes x j cover 128 pixels
#define LDGX(tt, ck) do {                                                              \
    int bb = (tt) >> 7, hh = (tt) & 127;                                               \
    _Pragma("unroll") for (int ci = 0; ci < 2; ci++)                                   \
    _Pragma("unroll") for (int dy = 0; dy < 2; dy++)                                   \
    _Pragma("unroll") for (int j = 0; j < 4; j++)                                      \
        pf[ci][dy][j] = *(const float2*)(x +                                           \
            (((size_t)bb * 96 + (ck) * 16 + 2 * wid + ci) * 256                        \
             + 2 * hh + dy) * 256 + 2 * (lane + 32 * j));                              \
} while (0)

// stats (raw f32) + fp16 convert + swizzled STS.128 of pf into buffer sbuf_
#define STAGE(sbuf_) do {                                                              \
    _Pragma("unroll") for (int j = 0; j < 4; j++) {                                    \
        const int p = lane + 32 * j;                                                   \
        float2 v00 = pf[0][0][j], v01 = pf[0][1][j];                                   \
        float2 v10 = pf[1][0][j], v11 = pf[1][1][j];                                   \
        ssum_t[j] += v00.x + v10.x;                                                    \
        ssq_t[j]  += v00.x * v00.x + v00.y * v00.y + v01.x * v01.x + v01.y * v01.y     \
                   + v10.x * v10.x + v10.y * v10.y + v11.x * v11.x + v11.y * v11.y;    \
        __half2 h0 = __floats2half2_rn(v00.x, v00.y);                                  \
        __half2 h1 = __floats2half2_rn(v01.x, v01.y);                                  \
        __half2 h2 = __floats2half2_rn(v10.x, v10.y);                                  \
        __half2 h3 = __floats2half2_rn(v11.x, v11.y);                                  \
        asm volatile("st.shared.v4.b32 [%0], {%1,%2,%3,%4};"                           \
                     :: "r"((sbuf_) + p * 128 + ((wid ^ (p & 7)) << 4)),               \
                        "r"(*(uint32_t*)&h0), "r"(*(uint32_t*)&h1),                    \
                        "r"(*(uint32_t*)&h2), "r"(*(uint32_t*)&h3) : "memory");        \
    } } while (0)

// one k=16 MMA step: ldmatrix A(4 tiles) + B(3 x4) + 24 HMMA
#define MMA_STEP(s_) do {                                                              \
    uint32_t ua[4][4], ub[6][2];                                                       \
    const uint32_t xa = (uint32_t)((((2 * (s_) + ga_sel) ^ l7)) << 4);                 \
    const uint32_t xb = (uint32_t)((((2 * (s_) + gb_sel) ^ l7)) << 4);                 \
    _Pragma("unroll") for (int mt = 0; mt < 4; mt++)                                   \
        asm volatile("ldmatrix.sync.aligned.m8n8.x4.shared.b16 {%0,%1,%2,%3}, [%4];"   \
            : "=r"(ua[mt][0]), "=r"(ua[mt][1]), "=r"(ua[mt][2]), "=r"(ua[mt][3])       \
            : "r"(abuf + arow_off + mt * 2048 + xa));                                  \
    _Pragma("unroll") for (int p = 0; p < 3; p++)                                      \
        asm volatile("ldmatrix.sync.aligned.m8n8.x4.shared.b16 {%0,%1,%2,%3}, [%4];"   \
            : "=r"(ub[2 * p][0]), "=r"(ub[2 * p][1]),                                  \
              "=r"(ub[2 * p + 1][0]), "=r"(ub[2 * p + 1][1])                           \
            : "r"(wck + brow_off + p * 2048 + xb));                                    \
    _Pragma("unroll") for (int mt = 0; mt < 4; mt++)                                   \
    _Pragma("unroll") for (int nt = 0; nt < 6; nt++)                                   \
        asm volatile("mma.sync.aligned.m16n8k16.row.col.f32.f16.f16.f32 "              \
            "{%0,%1,%2,%3}, {%4,%5,%6,%7}, {%8,%9}, {%0,%1,%2,%3};"                    \
            : "+f"(acc[mt][nt][0]), "+f"(acc[mt][nt][1]),                              \
              "+f"(acc[mt][nt][2]), "+f"(acc[mt][nt][3])                               \
            : "r"(ua[mt][0]), "r"(ua[mt][1]), "r"(ua[mt][2]), "r"(ua[mt][3]),          \
              "r"(ub[nt][0]), "r"(ub[nt][1]));                                         \
    } while (0)

__global__ void __launch_bounds__(256, 1)
pm_main(const float* __restrict__ x, float* __restrict__ out) {
    extern __shared__ char smem[];
    const uint32_t sb = smem_u32(smem);
    const int tid = threadIdx.x, lane = tid & 31, wid = tid >> 5;
    const int gid = lane >> 2, t4 = lane & 3;
    const int wh = wid >> 2, cpn = wid & 3;    // MMA warp grid: 2 (M) x 4 (N)
    const int l7 = lane & 7;

    const uint32_t arow_off = (uint32_t)((wh * 64 + l7 + ((lane >> 3) & 1) * 8) * 128);
    const uint32_t brow_off = (uint32_t)((cpn * 48 + l7 + (lane >> 4) * 8) * 128);
    const int ga_sel = lane >> 4;          // A k-granule bit
    const int gb_sel = (lane >> 3) & 1;    // B k-granule bit

    // ---- stage full weight matrix into SMEM (once per CTA) + st table ----
    {
        unsigned long long g0 =
            (unsigned long long)__cvta_generic_to_global((const char*)g_Wh + tid * 16);
        #pragma unroll
        for (int i = 0; i < 36; i++)
            asm volatile("cp.async.cg.shared.global [%0], [%1], 16;"
                         :: "r"(sb + SM_W + tid * 16 + i * 4096),
                            "l"(g0 + (unsigned long long)i * 4096) : "memory");
        asm volatile("cp.async.commit_group;" ::: "memory");
        asm volatile("cp.async.wait_group 0;" ::: "memory");
    }
    if (tid < 192) *(float2*)(smem + SM_ST + tid * 8) = g_st2[tid];

    float2 pf[2][2][4];
    float ssum_t[4] = {0, 0, 0, 0}, ssq_t[4] = {0, 0, 0, 0};

    // ---- prologue: stage chunk 0 of first tile, load chunk 1 ----
    int t = blockIdx.x;
    LDGX(t, 0);
    STAGE(sb + SM_A);                      // buf 0 holds chunk 0 (stats accumulated)
    LDGX(t, 1);
    __syncthreads();

    for (; t < NTILE; t += 148) {
        const int b = t >> 7, h = t & 127;
        const bool more = (t + 148 < NTILE);

        float acc[4][6][4];
        #pragma unroll
        for (int i = 0; i < 4; i++)
        #pragma unroll
        for (int j = 0; j < 6; j++)
        #pragma unroll
        for (int q = 0; q < 4; q++) acc[i][j][q] = 0.f;

        #pragma unroll 1
        for (int ck = 0; ck < 6; ++ck) {
            const int bm = (ck < 3) ? ck : ck - 3;               // g%3
            int bsx = ck + 1; bsx = (bsx < 3) ? bsx : ((bsx < 6) ? bsx - 3 : 0);
            const uint32_t abuf = sb + SM_A + (uint32_t)(bm << 14);
            const uint32_t sbuf = sb + SM_A + (uint32_t)(bsx << 14);
            const uint32_t wck  = sb + SM_W + (uint32_t)(ck * 24576);

            // flush completed tile stats before staging leaks into next tile
            if (ck == 5) {
                #pragma unroll
                for (int j = 0; j < 4; j++) {
                    int p = lane + 32 * j;
                    *(float*)(smem + SM_RED + (wid * 128 + p) * 4)        = ssum_t[j];
                    *(float*)(smem + SM_RED + 4096 + (wid * 128 + p) * 4) = ssq_t[j];
                    ssum_t[j] = 0.f; ssq_t[j] = 0.f;
                }
            }

            MMA_STEP(0); MMA_STEP(1);
            if (ck < 5 || more) STAGE(sbuf);       // chunk ck+1 (next tile ch0 at ck==5)
            MMA_STEP(2); MMA_STEP(3);
            if (ck < 4)      LDGX(t, ck + 2);      // chunk ck+2 of this tile
            else if (more)   LDGX(t + 148, ck - 4);// next tile ch 0 (ck=4) / ch 1 (ck=5)
            __syncthreads();                       // STS(ck+1) visible; buffers rotate
        }

        // ---- LN stats reduce (RED written at iter-5 top, fenced by iter-5 sync) ----
        if (tid < 128) {
            float s = 0.f, qq = 0.f;
            #pragma unroll
            for (int w = 0; w < 8; w++) {
                s  += *(float*)(smem + SM_RED + (w * 128 + tid) * 4);
                qq += *(float*)(smem + SM_RED + 4096 + (w * 128 + tid) * 4);
            }
            float mu = s * (1.f / 192.f);
            float var = qq * (1.f / 384.f) - mu * mu;
            *(float*)(smem + SM_MU + tid * 4) = mu;
            *(float*)(smem + SM_RR + tid * 4) = rsqrtf(var + 1e-5f);
        }
        __syncthreads();

        // ---- fused epilogue from register accumulators ----
        float* ob = out + ((size_t)b * 16384 + (size_t)h * 128) * 192;
        #pragma unroll
        for (int mt = 0; mt < 4; mt++) {
            int row0 = wh * 64 + mt * 16 + gid;
            float mu0 = *(float*)(smem + SM_MU + row0 * 4);
            float r0  = *(float*)(smem + SM_RR + row0 * 4);
            float mu1 = *(float*)(smem + SM_MU + (row0 + 8) * 4);
            float r1  = *(float*)(smem + SM_RR + (row0 + 8) * 4);
            #pragma unroll
            for (int nt = 0; nt < 6; nt++) {
                int cb = cpn * 48 + nt * 8 + 2 * t4;
                float2 st0 = *(const float2*)(smem + SM_ST + cb * 8);
                float2 st1 = *(const float2*)(smem + SM_ST + cb * 8 + 8);
                float2 v0, v1;
                v0.x = r0 * (acc[mt][nt][0] - mu0 * st0.x) + st0.y;
                v0.y = r0 * (acc[mt][nt][1] - mu0 * st1.x) + st1.y;
                v1.x = r1 * (acc[mt][nt][2] - mu1 * st0.x) + st0.y;
                v1.y = r1 * (acc[mt][nt][3] - mu1 * st1.x) + st1.y;
                *(float2*)(ob + (size_t)row0 * 192 + cb)       = v0;
                *(float2*)(ob + (size_t)(row0 + 8) * 192 + cb) = v1;
            }
        }
    }
}

extern "C" void kernel_launch(void* const* d_in, const int* in_sizes, int n_in,
                              void* d_out, int out_size) {
    const float* x  = (const float*)d_in[0];
    const float* nw = (const float*)d_in[1];
    const float* nb = (const float*)d_in[2];
    const float* wr = (const float*)d_in[3];
    float* out = (float*)d_out;
    (void)in_sizes; (void)n_in; (void)out_size;

    static int cfg = 0;
    if (!cfg) {
        cudaFuncSetAttribute(pm_main, cudaFuncAttributeMaxDynamicSharedMemorySize, SMEM_SZ);
        cfg = 1;
    }
    pm_prep<<<480, 256>>>(nw, nb, wr);
    pm_main<<<148, 256, SMEM_SZ>>>(x, out);
}